// round 4
// baseline (speedup 1.0000x reference)
#include <cuda_runtime.h>

#define Bsz   128
#define TM1   255
#define NIN   256
#define Hd    256
#define BT    (Bsz * TM1)      /* 32640 */
#define G4H   1024

// ---------------- device scratch (static allocation only) ----------------
__device__ float    g_G[(size_t)BT * G4H];   // 133.7 MB: pre-activations x_tilde@W + b
__device__ float    g_h[2][Bsz * Hd];        // ping-pong hidden state
__device__ unsigned g_bar;                   // grid barrier counter

__global__ void reset_kernel() { g_bar = 0u; }

// ---------------- kernel 1: alpha (softmax over inputs) + X_tilde --------
// alpha[b,n] = softmax_n( sum_t X[b,t,n] * W_attn[2H + t] )   (shift-invariance
// kills the h/c/b_attn terms). X_tilde[b,t,n] = alpha[b,n] * X[b,t,n].
__global__ __launch_bounds__(256) void alpha_kernel(const float* __restrict__ X,
                                                    const float* __restrict__ W_attn,
                                                    float* __restrict__ out_xt) {
    __shared__ float wx[TM1];
    __shared__ float red[256];
    const int b = blockIdx.x;
    const int n = threadIdx.x;
    if (n < TM1) wx[n] = W_attn[2 * Hd + n];
    __syncthreads();

    const float* Xb = X + (size_t)b * TM1 * NIN;
    float e = 0.f;
#pragma unroll 5
    for (int t = 0; t < TM1; t++) e = fmaf(Xb[t * NIN + n], wx[t], e);

    // block softmax over 256 lanes
    red[n] = e; __syncthreads();
    for (int s = 128; s > 0; s >>= 1) {
        if (n < s) red[n] = fmaxf(red[n], red[n + s]);
        __syncthreads();
    }
    float m = red[0];
    __syncthreads();
    float p = expf(e - m);
    red[n] = p; __syncthreads();
    for (int s = 128; s > 0; s >>= 1) {
        if (n < s) red[n] += red[n + s];
        __syncthreads();
    }
    const float a = p / red[0];

    float* outb = out_xt + (size_t)b * TM1 * NIN;
#pragma unroll 5
    for (int t = 0; t < TM1; t++) outb[t * NIN + n] = a * Xb[t * NIN + n];
}

// ---------------- kernel 2: G = X_tilde @ W_lstm + b_lstm ----------------
// A: [BT,256] row-major (read from d_out X_tilde region), W: [256,1024].
__global__ __launch_bounds__(256, 2) void gemm_kernel(const float* __restrict__ A,
                                                      const float* __restrict__ W,
                                                      const float* __restrict__ bias) {
    __shared__ float As[8][128];
    __shared__ float Bs[8][128];
    const int tid  = threadIdx.x;
    const int row0 = blockIdx.y * 128;
    const int col0 = blockIdx.x * 128;

    float acc[8][8];
#pragma unroll
    for (int i = 0; i < 8; i++)
#pragma unroll
        for (int j = 0; j < 8; j++) acc[i][j] = 0.f;

    const int tr = (tid >> 4) << 3;
    const int tc = (tid & 15) << 3;
    const int am = tid >> 1,  ak = (tid & 1) << 2;
    const int bk = tid >> 5,  bc = (tid & 31) << 2;

    for (int k0 = 0; k0 < 256; k0 += 8) {
        float4 av = *(const float4*)(A + (size_t)(row0 + am) * 256 + k0 + ak);
        As[ak + 0][am] = av.x; As[ak + 1][am] = av.y;
        As[ak + 2][am] = av.z; As[ak + 3][am] = av.w;
        float4 bv = *(const float4*)(W + (size_t)(k0 + bk) * 1024 + col0 + bc);
        *(float4*)&Bs[bk][bc] = bv;
        __syncthreads();
#pragma unroll
        for (int k = 0; k < 8; k++) {
            float a[8], bb[8];
            *(float4*)&a[0]  = *(const float4*)&As[k][tr];
            *(float4*)&a[4]  = *(const float4*)&As[k][tr + 4];
            *(float4*)&bb[0] = *(const float4*)&Bs[k][tc];
            *(float4*)&bb[4] = *(const float4*)&Bs[k][tc + 4];
#pragma unroll
            for (int i = 0; i < 8; i++)
#pragma unroll
                for (int j = 0; j < 8; j++)
                    acc[i][j] = fmaf(a[i], bb[j], acc[i][j]);
        }
        __syncthreads();
    }

#pragma unroll
    for (int i = 0; i < 8; i++) {
        const size_t r = (size_t)(row0 + tr + i) * G4H + col0 + tc;
#pragma unroll
        for (int j = 0; j < 8; j += 4) {
            float4 o;
            o.x = acc[i][j + 0] + bias[col0 + tc + j + 0];
            o.y = acc[i][j + 1] + bias[col0 + tc + j + 1];
            o.z = acc[i][j + 2] + bias[col0 + tc + j + 2];
            o.w = acc[i][j + 3] + bias[col0 + tc + j + 3];
            *(float4*)&g_G[r + j] = o;
        }
    }
}

// ---------------- kernel 3: persistent LSTM recurrence -------------------
// Grid = 128 CTAs x 128 threads, 1 CTA/SM (139 KB smem) => all co-resident,
// safe custom grid barrier. CTA (bblk,jblk) owns batches b0..b0+7, hidden
// units j0..j0+31. Each thread owns 2 (b,j) cells; c stays in registers.
#define RCTAS    128
#define RTHREADS 128
#define RSMEM    (256 * 32 * 16 + 8 * 256 * 4)   /* U slice + h tile = 139264 B */

__device__ __forceinline__ float sigm(float x) { return 1.f / (1.f + expf(-x)); }

__global__ void __launch_bounds__(RTHREADS, 1)
recur_kernel(const float* __restrict__ X,
             const float* __restrict__ U,
             float* __restrict__ out_enc) {
    extern __shared__ float4 smem4[];
    float4* Us4 = smem4;                 // [256*32] : (i,f,g,o) weights per (k, j)
    float4* hs4 = smem4 + 256 * 32;      // [8*64]   : 8 batch rows x 256 h values

    const int tid  = threadIdx.x;
    const int cta  = blockIdx.x;
    const int b0   = (cta & 15) * 8;     // 16 b-blocks
    const int j0   = (cta >> 4) * 32;    // 8 j-blocks
    const int jj   = tid & 31;
    const int bs   = tid >> 5;           // 0..3
    const int j    = j0 + jj;
    const int b_a  = b0 + bs;
    const int b_b  = b0 + bs + 4;

    // Load U slice once: Us4[k*32+jj] = (U[k][j], U[k][256+j], U[k][512+j], U[k][768+j])
    for (int idx = tid; idx < 256 * 32; idx += RTHREADS) {
        const int k  = idx >> 5;
        const int jc = j0 + (idx & 31);
        const float* Uk = U + (size_t)k * 1024;
        Us4[idx] = make_float4(Uk[jc], Uk[256 + jc], Uk[512 + jc], Uk[768 + jc]);
    }

    // init: h0 = c0 = X[b,0,0] broadcast over hidden dim
    const float x00a = X[(size_t)b_a * (TM1 * NIN)];
    const float x00b = X[(size_t)b_b * (TM1 * NIN)];
    g_h[0][b_a * Hd + j] = x00a;
    g_h[0][b_b * Hd + j] = x00b;
    float ca = x00a, cb = x00b;
    __threadfence();
    __syncthreads();
    if (tid == 0) atomicAdd(&g_bar, 1u);

    volatile unsigned* barp = &g_bar;

    for (int t = 0; t < TM1; t++) {
        // wait for all h writes of previous phase
        if (tid == 0) {
            const unsigned target = (unsigned)(t + 1) * RCTAS;
            while (*barp < target) { }
            __threadfence();
        }
        __syncthreads();

        // stage h rows b0..b0+7 into smem
        const float4* hsrc = (const float4*)(g_h[t & 1] + b0 * Hd);
        for (int i = tid; i < 8 * 64; i += RTHREADS) hs4[i] = hsrc[i];
        __syncthreads();

        // gate pre-activations from G + h @ U
        const size_t rowa = ((size_t)b_a * TM1 + t) * G4H;
        const size_t rowb = ((size_t)b_b * TM1 + t) * G4H;
        float ai = g_G[rowa + j],       af = g_G[rowa + 256 + j];
        float ag = g_G[rowa + 512 + j], ao = g_G[rowa + 768 + j];
        float bi = g_G[rowb + j],       bf = g_G[rowb + 256 + j];
        float bg = g_G[rowb + 512 + j], bo = g_G[rowb + 768 + j];

        const float4* ha4 = hs4 + bs * 64;
        const float4* hb4 = hs4 + (bs + 4) * 64;
#pragma unroll 8
        for (int k4 = 0; k4 < 64; k4++) {
            const float4 ha = ha4[k4];
            const float4 hb = hb4[k4];
            float4 u;
            u = Us4[(k4 * 4 + 0) * 32 + jj];
            ai = fmaf(ha.x, u.x, ai); af = fmaf(ha.x, u.y, af);
            ag = fmaf(ha.x, u.z, ag); ao = fmaf(ha.x, u.w, ao);
            bi = fmaf(hb.x, u.x, bi); bf = fmaf(hb.x, u.y, bf);
            bg = fmaf(hb.x, u.z, bg); bo = fmaf(hb.x, u.w, bo);
            u = Us4[(k4 * 4 + 1) * 32 + jj];
            ai = fmaf(ha.y, u.x, ai); af = fmaf(ha.y, u.y, af);
            ag = fmaf(ha.y, u.z, ag); ao = fmaf(ha.y, u.w, ao);
            bi = fmaf(hb.y, u.x, bi); bf = fmaf(hb.y, u.y, bf);
            bg = fmaf(hb.y, u.z, bg); bo = fmaf(hb.y, u.w, bo);
            u = Us4[(k4 * 4 + 2) * 32 + jj];
            ai = fmaf(ha.z, u.x, ai); af = fmaf(ha.z, u.y, af);
            ag = fmaf(ha.z, u.z, ag); ao = fmaf(ha.z, u.w, ao);
            bi = fmaf(hb.z, u.x, bi); bf = fmaf(hb.z, u.y, bf);
            bg = fmaf(hb.z, u.z, bg); bo = fmaf(hb.z, u.w, bo);
            u = Us4[(k4 * 4 + 3) * 32 + jj];
            ai = fmaf(ha.w, u.x, ai); af = fmaf(ha.w, u.y, af);
            ag = fmaf(ha.w, u.z, ag); ao = fmaf(ha.w, u.w, ao);
            bi = fmaf(hb.w, u.x, bi); bf = fmaf(hb.w, u.y, bf);
            bg = fmaf(hb.w, u.z, bg); bo = fmaf(hb.w, u.w, bo);
        }

        // LSTM cell (Keras gate order i,f,g,o)
        ca = sigm(af) * ca + sigm(ai) * tanhf(ag);
        const float hna = sigm(ao) * tanhf(ca);
        cb = sigm(bf) * cb + sigm(bi) * tanhf(bg);
        const float hnb = sigm(bo) * tanhf(cb);

        g_h[(t + 1) & 1][b_a * Hd + j] = hna;
        g_h[(t + 1) & 1][b_b * Hd + j] = hnb;
        out_enc[((size_t)b_a * TM1 + t) * Hd + j] = hna;
        out_enc[((size_t)b_b * TM1 + t) * Hd + j] = hnb;

        __threadfence();
        __syncthreads();
        if (tid == 0) atomicAdd(&g_bar, 1u);
    }
}

// ---------------- launch ----------------
extern "C" void kernel_launch(void* const* d_in, const int* in_sizes, int n_in,
                              void* d_out, int out_size) {
    const float* X      = (const float*)d_in[0];
    const float* W_attn = (const float*)d_in[1];
    /* b_attn = d_in[2] : cancels in softmax */
    const float* W_lstm = (const float*)d_in[3];
    const float* U_lstm = (const float*)d_in[4];
    const float* b_lstm = (const float*)d_in[5];

    float* out     = (float*)d_out;
    float* out_xt  = out;                             // X_tilde  (B,Tm1,N)
    float* out_enc = out + (size_t)Bsz * TM1 * NIN;   // X_encoded (B,Tm1,H)

    cudaFuncSetAttribute(recur_kernel,
                         cudaFuncAttributeMaxDynamicSharedMemorySize, RSMEM);

    reset_kernel<<<1, 1>>>();
    alpha_kernel<<<Bsz, 256>>>(X, W_attn, out_xt);
    gemm_kernel<<<dim3(8, TM1), 256>>>(out_xt, W_lstm, b_lstm);
    recur_kernel<<<RCTAS, RTHREADS, RSMEM>>>(X, U_lstm, out_enc);
}